// round 6
// baseline (speedup 1.0000x reference)
#include <cuda_runtime.h>
#include <cstdint>

#define NROWS 16384
#define DIN   4096
#define DOUT  4096
#define RNK   64
#define KTOP  8

#define DIN4  (DIN/4)    // 1024
#define DOUT4 (DOUT/4)   // 1024

#define NBLK  256        // co-resident: <= 2 CTAs/SM x 148 SMs
#define THR   512        // 16 warps
#define RPW   4          // rows per warp in phase A
#define RPB   64         // rows per block = 16 warps * 4  (256*64 = 16384 exactly)

#define NTILE 32         // 128-wide output tiles (4096/128)
#define NSPL  8          // row splits in phase B: 32*8 = 256 items = 1 per block
#define RSPL  2048       // rows per split (8*2048 = 16384 exactly)

// ---- scratch (device globals; no allocations allowed) ----
__device__ float4 g_G[NROWS * 2];                  // gathered*scaled values, [n][8]
__device__ uint2  g_pidx[NROWS];                   // 8x 6-bit indices packed as bytes
__device__ __align__(16) float g_uwT[RNK * DOUT];  // up_w transposed to [64][4096]
__device__ unsigned g_cnt;                         // grid barrier arrival count (zero-init)
__device__ unsigned g_gen;                         // grid barrier generation

__device__ __forceinline__ void grid_barrier()
{
    __threadfence();
    __syncthreads();
    if (threadIdx.x == 0) {
        unsigned gen = *(volatile unsigned*)&g_gen;      // read BEFORE arriving
        if (atomicAdd(&g_cnt, 1u) == NBLK - 1u) {
            atomicExch(&g_cnt, 0u);
            __threadfence();
            atomicAdd(&g_gen, 1u);
        } else {
            while (*(volatile unsigned*)&g_gen == gen) { }
        }
    }
    __syncthreads();
}

__global__ __launch_bounds__(THR, 2) void moe_fused(
    const float* __restrict__ x, const float* __restrict__ dw,
    const float* __restrict__ uw, const float* __restrict__ tv,
    const long long* __restrict__ ti, float* __restrict__ out)
{
    __shared__ float4 Wsm[RNK * 32];   // 32 KB: phase A down_w chunk / phase B up_wT tile
    __shared__ uint2  sidx[RPB];

    const int tid  = threadIdx.x;
    const int wid  = tid >> 5;         // 0..15
    const int lane = tid & 31;
    const int bid  = blockIdx.x;

    // ================= phase T: transpose up_w -> g_uwT [64][4096] ============
    for (int i = bid * THR + tid; i < RNK * DOUT; i += NBLK * THR) {
        int r = i >> 12, o = i & (DOUT - 1);
        g_uwT[i] = uw[o * RNK + r];               // coalesced store
    }

    // ================= phase A: sparse down-projection ========================
    // dtype detection, in-bounds for both int32 and int64 index data:
    // int64 indices in [0,64) have zero high words at odd int32 positions 1..15;
    // int32 data there holds real distinct-per-row indices -> OR != 0.
    const int* t32base = (const int*)ti;
    const bool is64 = ((t32base[1] | t32base[3] | t32base[5] | t32base[7] |
                        t32base[9] | t32base[11] | t32base[13] | t32base[15]) == 0);

    const int row0 = bid * RPB;

    // pack top-k indices: lanes 0..3 of each warp handle one of its 4 rows
    if (lane < RPW) {
        int r   = wid * RPW + lane;
        int row = row0 + r;
        unsigned lo = 0, hi = 0;
        if (is64) {
            const long long* t64 = ti + (size_t)row * KTOP;
            #pragma unroll
            for (int k = 0; k < 4; k++) {
                lo |= ((unsigned)t64[k]     & 63u) << (8 * k);
                hi |= ((unsigned)t64[4 + k] & 63u) << (8 * k);
            }
        } else {
            const int* t32 = t32base + (size_t)row * KTOP;
            #pragma unroll
            for (int k = 0; k < 4; k++) {
                lo |= ((unsigned)t32[k]     & 63u) << (8 * k);
                hi |= ((unsigned)t32[4 + k] & 63u) << (8 * k);
            }
        }
        uint2 p; p.x = lo; p.y = hi;
        sidx[r]    = p;
        g_pidx[row] = p;
    }
    __syncthreads();

    uint2 pk[RPW];
    #pragma unroll
    for (int r4 = 0; r4 < RPW; r4++) pk[r4] = sidx[wid * RPW + r4];

    float acc[RPW][8];
    #pragma unroll
    for (int i = 0; i < RPW; i++)
        #pragma unroll
        for (int k = 0; k < 8; k++) acc[i][k] = 0.f;

    const float4* x4  = (const float4*)x;
    const float4* dw4 = (const float4*)dw;

    #pragma unroll 1
    for (int c = 0; c < DIN4 / 32; c++) {         // 32 chunks of 128 cols
        // stage down_w chunk [64][128] into SMEM (coalesced float4, 4 per thread)
        #pragma unroll
        for (int t = 0; t < 4; t++) {
            int lin = tid + t * THR;              // 0..2047
            Wsm[lin] = dw4[(lin >> 5) * DIN4 + c * 32 + (lin & 31)];
        }
        __syncthreads();

        #pragma unroll
        for (int r4 = 0; r4 < RPW; r4++) {
            int row = row0 + wid * RPW + r4;
            float4 xv = x4[(size_t)row * DIN4 + c * 32 + lane];
            unsigned lo = pk[r4].x, hi = pk[r4].y;
            #pragma unroll
            for (int k = 0; k < 8; k++) {
                unsigned bits = (k < 4) ? lo : hi;
                unsigned idx  = (bits >> (8 * (k & 3))) & 63u;
                float4 wv = Wsm[idx * 32 + lane];  // uniform idx per warp -> conflict-free
                float a = acc[r4][k];
                a = fmaf(xv.x, wv.x, a);
                a = fmaf(xv.y, wv.y, a);
                a = fmaf(xv.z, wv.z, a);
                a = fmaf(xv.w, wv.w, a);
                acc[r4][k] = a;
            }
        }
        __syncthreads();
    }

    // reduce across lanes, scale, store G
    #pragma unroll
    for (int r4 = 0; r4 < RPW; r4++) {
        int row = row0 + wid * RPW + r4;
        #pragma unroll
        for (int k = 0; k < 8; k++) {
            float vsum = acc[r4][k];
            vsum += __shfl_xor_sync(0xffffffffu, vsum, 16);
            vsum += __shfl_xor_sync(0xffffffffu, vsum, 8);
            vsum += __shfl_xor_sync(0xffffffffu, vsum, 4);
            vsum += __shfl_xor_sync(0xffffffffu, vsum, 2);
            vsum += __shfl_xor_sync(0xffffffffu, vsum, 1);
            if (lane == k) {
                ((float*)g_G)[(size_t)row * KTOP + k] = vsum * tv[(size_t)row * KTOP + k];
            }
        }
    }

    // ============ all G / pidx must be visible chip-wide ======================
    grid_barrier();

    // ================= phase B: sparse up-projection ==========================
    // one item per block: tile = bid & 31 (128 outputs), split = bid >> 5 (2048 rows)
    const float4* uwT4 = (const float4*)g_uwT;
    float4* out4 = (float4*)out;

    const int tile  = bid & (NTILE - 1);
    const int split = bid >> 5;
    const int ob4   = tile * 32;                  // float4 offset into DOUT4

    // stage up_wT tile [64][128] into SMEM
    #pragma unroll
    for (int t = 0; t < 4; t++) {
        int lin = tid + t * THR;
        Wsm[lin] = uwT4[(lin >> 5) * DOUT4 + ob4 + (lin & 31)];
    }
    __syncthreads();

    int n = split * RSPL + wid;                   // 128 iterations, stride 16, exact

    // software pipeline depth 2
    int np1 = n + 16, np2 = min(n + 32, NROWS - 1);
    uint2  p0 = g_pidx[n];
    float4 Ga0 = g_G[n * 2],   Gb0 = g_G[n * 2 + 1];
    uint2  p1 = g_pidx[np1];
    float4 Ga1 = g_G[np1 * 2], Gb1 = g_G[np1 * 2 + 1];

    #pragma unroll 1
    for (int it = 0; it < RSPL / 16; it++) {
        // issue prefetch for iteration it+2
        uint2  p2  = g_pidx[np2];
        float4 Ga2 = g_G[np2 * 2];
        float4 Gb2 = g_G[np2 * 2 + 1];

        float4 a; a.x = a.y = a.z = a.w = 0.f;
        float4 w;
        unsigned i0 =  p0.x        & 63u;
        unsigned i1 = (p0.x >> 8)  & 63u;
        unsigned i2 = (p0.x >> 16) & 63u;
        unsigned i3 = (p0.x >> 24) & 63u;
        unsigned i4 =  p0.y        & 63u;
        unsigned i5 = (p0.y >> 8)  & 63u;
        unsigned i6 = (p0.y >> 16) & 63u;
        unsigned i7 = (p0.y >> 24) & 63u;

        w = Wsm[i0 * 32 + lane];
        a.x = fmaf(Ga0.x, w.x, a.x); a.y = fmaf(Ga0.x, w.y, a.y); a.z = fmaf(Ga0.x, w.z, a.z); a.w = fmaf(Ga0.x, w.w, a.w);
        w = Wsm[i1 * 32 + lane];
        a.x = fmaf(Ga0.y, w.x, a.x); a.y = fmaf(Ga0.y, w.y, a.y); a.z = fmaf(Ga0.y, w.z, a.z); a.w = fmaf(Ga0.y, w.w, a.w);
        w = Wsm[i2 * 32 + lane];
        a.x = fmaf(Ga0.z, w.x, a.x); a.y = fmaf(Ga0.z, w.y, a.y); a.z = fmaf(Ga0.z, w.z, a.z); a.w = fmaf(Ga0.z, w.w, a.w);
        w = Wsm[i3 * 32 + lane];
        a.x = fmaf(Ga0.w, w.x, a.x); a.y = fmaf(Ga0.w, w.y, a.y); a.z = fmaf(Ga0.w, w.z, a.z); a.w = fmaf(Ga0.w, w.w, a.w);
        w = Wsm[i4 * 32 + lane];
        a.x = fmaf(Gb0.x, w.x, a.x); a.y = fmaf(Gb0.x, w.y, a.y); a.z = fmaf(Gb0.x, w.z, a.z); a.w = fmaf(Gb0.x, w.w, a.w);
        w = Wsm[i5 * 32 + lane];
        a.x = fmaf(Gb0.y, w.x, a.x); a.y = fmaf(Gb0.y, w.y, a.y); a.z = fmaf(Gb0.y, w.z, a.z); a.w = fmaf(Gb0.y, w.w, a.w);
        w = Wsm[i6 * 32 + lane];
        a.x = fmaf(Gb0.z, w.x, a.x); a.y = fmaf(Gb0.z, w.y, a.y); a.z = fmaf(Gb0.z, w.z, a.z); a.w = fmaf(Gb0.z, w.w, a.w);
        w = Wsm[i7 * 32 + lane];
        a.x = fmaf(Gb0.w, w.x, a.x); a.y = fmaf(Gb0.w, w.y, a.y); a.z = fmaf(Gb0.w, w.z, a.z); a.w = fmaf(Gb0.w, w.w, a.w);

        out4[(size_t)n * DOUT4 + ob4 + lane] = a;

        // rotate pipeline
        n = np1; np1 = np2; np2 = min(np1 + 16, NROWS - 1);
        p0 = p1; Ga0 = Ga1; Gb0 = Gb1;
        p1 = p2; Ga1 = Ga2; Gb1 = Gb2;
    }
}

// =====================================================================
extern "C" void kernel_launch(void* const* d_in, const int* in_sizes, int n_in,
                              void* d_out, int out_size)
{
    const float*     x  = (const float*)d_in[0];      // hidden_states [16384,4096]
    const float*     dw = (const float*)d_in[1];      // down_w [64,4096]
    const float*     uw = (const float*)d_in[2];      // up_w [4096,64]
    const float*     tv = (const float*)d_in[3];      // top_k_values [16384,8]
    const long long* ti = (const long long*)d_in[4];  // top_k_indices (i64/i32 auto)

    moe_fused<<<NBLK, THR>>>(x, dw, uw, tv, ti, (float*)d_out);
}

// round 8
// speedup vs baseline: 1.1773x; 1.1773x over previous
#include <cuda_runtime.h>
#include <cuda_bf16.h>
#include <cstdint>

#define NCTA 128
#define THR  256

// smem word offsets (4B words)
#define W_XH   0        // 128*36
#define W_XL   4608
#define W_DWH  9216     // 64*36
#define W_DWL  11520
#define W_UH   0        // 256*36 (reuses G1 staging region)
#define W_UL   9216
#define W_DSM  18432    // 128*66 f32
#define W_RH   26880    // 128*36
#define W_RL   31488
#define SMEM_SZ (36096*4)

// pre-split weights (bf16 hi/lo), 512KB each
__device__ unsigned short g_dwh[64*4096], g_dwl[64*4096];
__device__ unsigned short g_uwh[4096*64], g_uwl[4096*64];

static __device__ __forceinline__ uint32_t pk2(float lo, float hi) {
    uint32_t r; asm("cvt.rn.bf16x2.f32 %0, %1, %2;" : "=r"(r) : "f"(hi), "f"(lo)); return r;
}
static __device__ __forceinline__ void split4w(float4 v, uint32_t& h0, uint32_t& h1,
                                               uint32_t& l0, uint32_t& l1) {
    h0 = pk2(v.x, v.y); h1 = pk2(v.z, v.w);
    float ax = __uint_as_float(h0 << 16), ay = __uint_as_float(h0 & 0xffff0000u);
    float az = __uint_as_float(h1 << 16), aw = __uint_as_float(h1 & 0xffff0000u);
    l0 = pk2(v.x - ax, v.y - ay); l1 = pk2(v.z - az, v.w - aw);
}
static __device__ __forceinline__ void bmma(float d[4], const uint32_t a[4],
                                            uint32_t b0, uint32_t b1) {
    asm("mma.sync.aligned.m16n8k16.row.col.f32.bf16.bf16.f32 "
        "{%0,%1,%2,%3},{%4,%5,%6,%7},{%8,%9},{%0,%1,%2,%3};"
        : "+f"(d[0]), "+f"(d[1]), "+f"(d[2]), "+f"(d[3])
        : "r"(a[0]), "r"(a[1]), "r"(a[2]), "r"(a[3]), "r"(b0), "r"(b1));
}

// ---- prep: split dw (64x4096) and uw (4096x64) into bf16 hi/lo ----
__global__ void kprep(const float* __restrict__ dw, const float* __restrict__ uw) {
    int i = blockIdx.x * 256 + threadIdx.x;   // 0..524287
    float v = (i < 262144) ? dw[i] : uw[i - 262144];
    __nv_bfloat16 hb = __float2bfloat16(v);
    float l = v - __bfloat162float(hb);
    __nv_bfloat16 lb = __float2bfloat16(l);
    unsigned short hu = *(unsigned short*)&hb, lu = *(unsigned short*)&lb;
    if (i < 262144) { g_dwh[i] = hu; g_dwl[i] = lu; }
    else            { g_uwh[i - 262144] = hu; g_uwl[i - 262144] = lu; }
}

__global__ __launch_bounds__(THR, 1) void moe_mma(
    const float* __restrict__ x, const float* __restrict__ tv,
    const long long* __restrict__ ti, float* __restrict__ out)
{
    extern __shared__ uint32_t sm[];
    const int tid = threadIdx.x, wid = tid >> 5, lane = tid & 31;
    const int lr = lane >> 2, lc = lane & 3;     // fragment row-group / col-group
    const int rm = wid * 16;                     // warp's m-tile base row
    const int row0 = blockIdx.x * 128;

    // ---- pack top-k indices in registers (int32/int64 auto-detect, in-bounds) ----
    uint32_t plo = 0, phi = 0;
    {
        const int* t32b = (const int*)ti;
        bool is64 = ((t32b[1]|t32b[3]|t32b[5]|t32b[7]|t32b[9]|t32b[11]|t32b[13]|t32b[15]) == 0);
        if (tid < 128) {
            int row = row0 + tid;
            if (is64) {
                const long long* t = ti + (size_t)row * 8;
                #pragma unroll
                for (int k = 0; k < 4; k++) { plo |= ((uint32_t)t[k]&63u)<<(8*k); phi |= ((uint32_t)t[4+k]&63u)<<(8*k); }
            } else {
                const int* t = t32b + (size_t)row * 8;
                #pragma unroll
                for (int k = 0; k < 4; k++) { plo |= ((uint32_t)t[k]&63u)<<(8*k); phi |= ((uint32_t)t[4+k]&63u)<<(8*k); }
            }
        }
    }

    // ================== GEMM1: D1[128,64] = X_tile @ dw^T (bf16x3) ==================
    const float4* x4   = (const float4*)x;
    const uint4*  dwh4 = (const uint4*)g_dwh;    // 512 uint4 per rank-row
    const uint4*  dwl4 = (const uint4*)g_dwl;

    float acc[8][4];
    #pragma unroll
    for (int t = 0; t < 8; t++) { acc[t][0]=acc[t][1]=acc[t][2]=acc[t][3]=0.f; }

    float4 px[8]; uint4 pwh[2], pwl[2];
    #pragma unroll
    for (int j = 0; j < 8; j++) { int f = tid + j*256; px[j] = x4[(size_t)(row0 + (f>>4))*1024 + (f&15)]; }
    #pragma unroll
    for (int j = 0; j < 2; j++) { int f = tid + j*256; pwh[j] = dwh4[(f>>3)*512 + (f&7)]; pwl[j] = dwl4[(f>>3)*512 + (f&7)]; }

    #pragma unroll 1
    for (int c = 0; c < 64; c++) {
        __syncthreads();
        #pragma unroll
        for (int j = 0; j < 8; j++) {
            int f = tid + j*256, row = f>>4, q = f&15;
            uint32_t h0,h1,l0,l1; split4w(px[j], h0,h1,l0,l1);
            uint32_t wa = row*36 + q*2;
            *(uint2*)&sm[W_XH + wa] = make_uint2(h0,h1);
            *(uint2*)&sm[W_XL + wa] = make_uint2(l0,l1);
        }
        #pragma unroll
        for (int j = 0; j < 2; j++) {
            int f = tid + j*256, n = f>>3, qw = f&7;
            uint32_t wa = n*36 + qw*4;
            *(uint4*)&sm[W_DWH + wa] = pwh[j];
            *(uint4*)&sm[W_DWL + wa] = pwl[j];
        }
        __syncthreads();
        if (c < 63) {
            #pragma unroll
            for (int j = 0; j < 8; j++) { int f = tid + j*256; px[j] = x4[(size_t)(row0 + (f>>4))*1024 + (c+1)*16 + (f&15)]; }
            #pragma unroll
            for (int j = 0; j < 2; j++) { int f = tid + j*256; pwh[j] = dwh4[(f>>3)*512 + (c+1)*8 + (f&7)]; pwl[j] = dwl4[(f>>3)*512 + (c+1)*8 + (f&7)]; }
        }
        #pragma unroll
        for (int s = 0; s < 4; s++) {
            uint32_t ah[4], al[4];
            uint32_t wa = (rm + lr)*36 + s*8 + lc;
            ah[0] = sm[W_XH+wa]; ah[1] = sm[W_XH+wa+288]; ah[2] = sm[W_XH+wa+4]; ah[3] = sm[W_XH+wa+292];
            al[0] = sm[W_XL+wa]; al[1] = sm[W_XL+wa+288]; al[2] = sm[W_XL+wa+4]; al[3] = sm[W_XL+wa+292];
            #pragma unroll
            for (int t = 0; t < 8; t++) {
                uint32_t wb = (t*8 + lr)*36 + s*8 + lc;
                uint32_t bh0 = sm[W_DWH+wb], bh1 = sm[W_DWH+wb+4];
                uint32_t bl0 = sm[W_DWL+wb], bl1 = sm[W_DWL+wb+4];
                bmma(acc[t], ah, bh0, bh1);
                bmma(acc[t], ah, bl0, bl1);
                bmma(acc[t], al, bh0, bh1);
            }
        }
    }

    // ---- epilogue1: D1 frags -> Dsm, zero R ----
    __syncthreads();
    #pragma unroll
    for (int t = 0; t < 8; t++) {
        uint32_t wd = (rm + lr)*66 + t*8 + lc*2;
        *(float2*)&sm[W_DSM + wd]        = make_float2(acc[t][0], acc[t][1]);
        *(float2*)&sm[W_DSM + wd + 528]  = make_float2(acc[t][2], acc[t][3]);   // +8 rows
    }
    #pragma unroll
    for (int j = 0; j < 36; j++) sm[W_RH + tid + j*256] = 0;    // Rh+Rl contiguous (9216 words)
    __syncthreads();

    // prefetch G2 chunk 0 while gathering
    const uint4* uwh4 = (const uint4*)g_uwh;    // 8 uint4 per n-row
    const uint4* uwl4 = (const uint4*)g_uwl;
    uint4 pu[16];
    #pragma unroll
    for (int j = 0; j < 8; j++) { int f = tid + j*256, n = f>>3, qw = f&7; pu[j] = uwh4[n*8+qw]; pu[j+8] = uwl4[n*8+qw]; }

    // ---- gather * scale -> sparse R (bf16 split) ----
    if (tid < 128) {
        const float* tvr = tv + (size_t)(row0 + tid)*8;
        #pragma unroll
        for (int k = 0; k < 8; k++) {
            uint32_t idx = ((k < 4 ? plo : phi) >> (8*(k&3))) & 63u;
            float v = ((float*)&sm[W_DSM])[tid*66 + idx] * tvr[k];
            __nv_bfloat16 hb = __float2bfloat16(v);
            float l = v - __bfloat162float(hb);
            __nv_bfloat16 lb = __float2bfloat16(l);
            ((unsigned short*)&sm[W_RH])[tid*72 + idx] = *(unsigned short*)&hb;
            ((unsigned short*)&sm[W_RL])[tid*72 + idx] = *(unsigned short*)&lb;
        }
    }
    __syncthreads();

    // ---- load R fragments (register-resident for all of GEMM2) ----
    uint32_t Ah[4][4], Al[4][4];
    #pragma unroll
    for (int s = 0; s < 4; s++) {
        uint32_t wa = (rm + lr)*36 + s*8 + lc;
        Ah[s][0] = sm[W_RH+wa]; Ah[s][1] = sm[W_RH+wa+288]; Ah[s][2] = sm[W_RH+wa+4]; Ah[s][3] = sm[W_RH+wa+292];
        Al[s][0] = sm[W_RL+wa]; Al[s][1] = sm[W_RL+wa+288]; Al[s][2] = sm[W_RL+wa+4]; Al[s][3] = sm[W_RL+wa+292];
    }

    // ================== GEMM2: out[128,4096] = R[128,64] @ uw^T (bf16x3) ==================
    #pragma unroll 1
    for (int ch = 0; ch < 16; ch++) {
        __syncthreads();
        #pragma unroll
        for (int j = 0; j < 8; j++) {
            int f = tid + j*256, n = f>>3, qw = f&7;
            uint32_t wa = n*36 + qw*4;
            *(uint4*)&sm[W_UH + wa] = pu[j];
            *(uint4*)&sm[W_UL + wa] = pu[j+8];
        }
        __syncthreads();
        if (ch < 15) {
            #pragma unroll
            for (int j = 0; j < 8; j++) {
                int f = tid + j*256, n = f>>3, qw = f&7;
                pu[j]   = uwh4[((ch+1)*256 + n)*8 + qw];
                pu[j+8] = uwl4[((ch+1)*256 + n)*8 + qw];
            }
        }
        #pragma unroll 4
        for (int t = 0; t < 32; t++) {
            float d[4] = {0.f, 0.f, 0.f, 0.f};
            #pragma unroll
            for (int s = 0; s < 4; s++) {
                uint32_t wb = (t*8 + lr)*36 + s*8 + lc;
                uint32_t bh0 = sm[W_UH+wb], bh1 = sm[W_UH+wb+4];
                uint32_t bl0 = sm[W_UL+wb], bl1 = sm[W_UL+wb+4];
                bmma(d, Ah[s], bh0, bh1);
                bmma(d, Ah[s], bl0, bl1);
                bmma(d, Al[s], bh0, bh1);
            }
            size_t o = (size_t)(row0 + rm + lr)*4096 + ch*256 + t*8 + lc*2;
            *(float2*)&out[o]           = make_float2(d[0], d[1]);
            *(float2*)&out[o + 8*4096]  = make_float2(d[2], d[3]);
        }
    }
}

extern "C" void kernel_launch(void* const* d_in, const int* in_sizes, int n_in,
                              void* d_out, int out_size)
{
    const float*     x  = (const float*)d_in[0];      // [16384,4096]
    const float*     dw = (const float*)d_in[1];      // [64,4096]
    const float*     uw = (const float*)d_in[2];      // [4096,64]
    const float*     tv = (const float*)d_in[3];      // [16384,8]
    const long long* ti = (const long long*)d_in[4];  // [16384,8] i32/i64

    cudaFuncSetAttribute(moe_mma, cudaFuncAttributeMaxDynamicSharedMemorySize, SMEM_SZ);
    kprep<<<2048, 256>>>(dw, uw);
    moe_mma<<<NCTA, THR, SMEM_SZ>>>(x, tv, ti, (float*)d_out);
}